// round 8
// baseline (speedup 1.0000x reference)
#include <cuda_runtime.h>
#include <cstdint>

#define T_SEQ 1024
#define BATCH 256
#define ISZ   128
#define HSZ   64
#define GSZ   256   // 4*H
#define NBP   128   // BATCH/2 (batch pairs)
#define NCLS  10
#define PAD   72    // smem row pitch (floats) for conflict-free LDS.64

typedef unsigned long long ull;

// Scratch (device globals — allocation-free per harness rules)
// Layout: [t][bp][g] of float2{batch 2bp, batch 2bp+1}
__device__ float2 g_xproj[(size_t)T_SEQ * NBP * GSZ];   // 268 MB
__device__ ull    g_hT[NBP * HSZ];                      // final hidden, packed pairs

// ---------- helpers ----------
union F2U { float2 f2; ull u; };

__device__ __forceinline__ ull pack2(float lo, float hi) {
    F2U t; t.f2 = make_float2(lo, hi); return t.u;
}
__device__ __forceinline__ float2 unpack2(ull v) {
    F2U t; t.u = v; return t.f2;
}
__device__ __forceinline__ ull ffma2(ull a, ull b, ull c) {
    ull d;
    asm("fma.rn.f32x2 %0, %1, %2, %3;" : "=l"(d) : "l"(a), "l"(b), "l"(c));
    return d;
}
__device__ __forceinline__ ull fadd2(ull a, ull b) {
    ull d;
    asm("add.rn.f32x2 %0, %1, %2;" : "=l"(d) : "l"(a), "l"(b));
    return d;
}
__device__ __forceinline__ unsigned f2tf32(float f) {
    unsigned r;
    asm("cvt.rna.tf32.f32 %0, %1;" : "=r"(r) : "f"(f));
    return r;
}
__device__ __forceinline__ float ex2_ap(float x) {
    float y; asm("ex2.approx.f32 %0, %1;" : "=f"(y) : "f"(x)); return y;
}
__device__ __forceinline__ float rcp_ap(float x) {
    float y; asm("rcp.approx.f32 %0, %1;" : "=f"(y) : "f"(x)); return y;
}
// sigmoid(x) = 1/(1+2^(-x*log2e))   (2 MUFU + 2 ALU, ~1e-6 err)
__device__ __forceinline__ float sigm_f(float x) {
    return rcp_ap(1.0f + ex2_ap(-1.4426950408889634f * x));
}
// tanh(x) = 1 - 2/(1+2^(x*2*log2e))
__device__ __forceinline__ float tanh_f(float x) {
    return fmaf(-2.0f, rcp_ap(1.0f + ex2_ap(2.8853900817779268f * x)), 1.0f);
}

// =====================================================================
// Kernel A: x_proj[t][bp][g] = {x[2bp,t]·W_ih[g] + bias, x[2bp+1,t]·W_ih[g] + bias}
// tf32 mma.sync. SMEM holds tf32 bits in a k-interleaved layout so each
// mma fragment element-pair (k, k+4) is one LDS.64. No cvt in inner loop.
// k-permutation within each 8-chunk: slots = [k0,k4,k1,k5,k2,k6,k3,k7]
// =====================================================================
__global__ __launch_bounds__(128) void xproj_kernel(
    const float* __restrict__ x, const float* __restrict__ W_ih,
    const float* __restrict__ b_ih, const float* __restrict__ b_hh)
{
    __shared__ unsigned As[2][16][PAD];   // tf32 bits, k-permuted
    __shared__ unsigned Ws[128][PAD];
    __shared__ float bias_s[128];

    const int tid  = threadIdx.x;
    const int warp = tid >> 5, lane = tid & 31;
    const int gid  = lane >> 2, tig = lane & 3;   // mma groupID / threadID-in-group
    const int gbase = blockIdx.x * 128;
    const int t0    = blockIdx.y * 16;
    const int bp    = blockIdx.z;
    const int b0g   = bp * 2;

    bias_s[tid] = b_ih[gbase + tid] + b_hh[gbase + tid];

    float acc[2][4][4];
    #pragma unroll
    for (int b = 0; b < 2; b++)
        #pragma unroll
        for (int n = 0; n < 4; n++)
            #pragma unroll
            for (int i = 0; i < 4; i++) acc[b][n][i] = 0.f;

    for (int kc = 0; kc < 128; kc += 64) {
        // ---- stage A: 2b x 16t x 8chunks = 256 units, 2 iters ----
        #pragma unroll
        for (int r = 0; r < 2; ++r) {
            int u   = tid + r * 128;
            int b   = u >> 7;
            int rem = u & 127;
            int tt  = rem >> 3;
            int ch  = rem & 7;
            const float* src = &x[(((size_t)(b0g + b)) * T_SEQ + (t0 + tt)) * ISZ + kc + ch * 8];
            float4 e = *(const float4*)src;
            float4 o = *(const float4*)(src + 4);
            uint4 v0 = make_uint4(f2tf32(e.x), f2tf32(o.x), f2tf32(e.y), f2tf32(o.y));
            uint4 v1 = make_uint4(f2tf32(e.z), f2tf32(o.z), f2tf32(e.w), f2tf32(o.w));
            *(uint4*)&As[b][tt][ch * 8]     = v0;
            *(uint4*)&As[b][tt][ch * 8 + 4] = v1;
        }
        // ---- stage W: 128g x 8chunks = 1024 units, 8 iters ----
        #pragma unroll
        for (int r = 0; r < 8; ++r) {
            int u  = tid + r * 128;
            int gg = u >> 3;
            int ch = u & 7;
            const float* src = &W_ih[((size_t)(gbase + gg)) * ISZ + kc + ch * 8];
            float4 e = *(const float4*)src;
            float4 o = *(const float4*)(src + 4);
            uint4 v0 = make_uint4(f2tf32(e.x), f2tf32(o.x), f2tf32(e.y), f2tf32(o.y));
            uint4 v1 = make_uint4(f2tf32(e.z), f2tf32(o.z), f2tf32(e.w), f2tf32(o.w));
            *(uint4*)&Ws[gg][ch * 8]     = v0;
            *(uint4*)&Ws[gg][ch * 8 + 4] = v1;
        }
        __syncthreads();

        #pragma unroll
        for (int ks = 0; ks < 8; ++ks) {
            const int sb = ks * 8 + 2 * tig;
            // A fragments: (k, k+4) pairs via single LDS.64
            uint2 a00 = *(const uint2*)&As[0][gid    ][sb];
            uint2 a01 = *(const uint2*)&As[0][gid + 8][sb];
            uint2 a10 = *(const uint2*)&As[1][gid    ][sb];
            uint2 a11 = *(const uint2*)&As[1][gid + 8][sb];
            #pragma unroll
            for (int nt = 0; nt < 4; nt++) {
                const int nl = warp * 32 + nt * 8 + gid;
                uint2 bb = *(const uint2*)&Ws[nl][sb];
                asm volatile(
                    "mma.sync.aligned.m16n8k8.row.col.f32.tf32.tf32.f32 "
                    "{%0,%1,%2,%3}, {%4,%5,%6,%7}, {%8,%9}, {%0,%1,%2,%3};"
                    : "+f"(acc[0][nt][0]), "+f"(acc[0][nt][1]),
                      "+f"(acc[0][nt][2]), "+f"(acc[0][nt][3])
                    : "r"(a00.x), "r"(a01.x), "r"(a00.y), "r"(a01.y),
                      "r"(bb.x), "r"(bb.y));
                asm volatile(
                    "mma.sync.aligned.m16n8k8.row.col.f32.tf32.tf32.f32 "
                    "{%0,%1,%2,%3}, {%4,%5,%6,%7}, {%8,%9}, {%0,%1,%2,%3};"
                    : "+f"(acc[1][nt][0]), "+f"(acc[1][nt][1]),
                      "+f"(acc[1][nt][2]), "+f"(acc[1][nt][3])
                    : "r"(a10.x), "r"(a11.x), "r"(a10.y), "r"(a11.y),
                      "r"(bb.x), "r"(bb.y));
            }
        }
        __syncthreads();
    }

    // Epilogue: add bias, write paired float2 (as float4 covering 2 adjacent g)
    #pragma unroll
    for (int nt = 0; nt < 4; nt++) {
        const int nl  = warp * 32 + nt * 8 + 2 * tig;
        const float bs0 = bias_s[nl], bs1 = bias_s[nl + 1];
        const int ggl = gbase + nl;
        const int tr0 = t0 + gid, tr1 = t0 + gid + 8;
        float4 v0 = make_float4(acc[0][nt][0] + bs0, acc[1][nt][0] + bs0,
                                acc[0][nt][1] + bs1, acc[1][nt][1] + bs1);
        float4 v1 = make_float4(acc[0][nt][2] + bs0, acc[1][nt][2] + bs0,
                                acc[0][nt][3] + bs1, acc[1][nt][3] + bs1);
        *(float4*)&g_xproj[((size_t)tr0 * NBP + bp) * GSZ + ggl] = v0;
        *(float4*)&g_xproj[((size_t)tr1 * NBP + bp) * GSZ + ggl] = v1;
    }
}

// =====================================================================
// Kernel B: recurrence. 128 CTAs (one batch pair), 512 threads.
// Thread pair (g, half) splits the k-sum; combine via intra-warp shfl.
// Activation work split across the lane pair. h-update spread over 128 threads.
// =====================================================================
__global__ __launch_bounds__(512, 1) void lstm_kernel(const float* __restrict__ W_hh)
{
    __shared__ __align__(16) ull h_s[HSZ];
    __shared__ ull gate_s[GSZ];

    const int tid  = threadIdx.x;
    const int g    = tid >> 1;
    const int half = tid & 1;         // which k-half this thread sums
    const int bp   = blockIdx.x;
    const int sec  = g >> 6;          // 0:i 1:f 2:g 3:o (warp-uniform)

    // Load this thread's 32 W_hh columns, duplicated into f32x2 pairs (64 regs)
    ull w2[32];
    {
        const float4* wrow = (const float4*)&W_hh[g * HSZ + half * 32];
        #pragma unroll
        for (int q = 0; q < 8; ++q) {
            float4 w = wrow[q];
            w2[q * 4 + 0] = pack2(w.x, w.x);
            w2[q * 4 + 1] = pack2(w.y, w.y);
            w2[q * 4 + 2] = pack2(w.z, w.z);
            w2[q * 4 + 3] = pack2(w.w, w.w);
        }
    }

    // c-state: threads 0..127 hold c for (j = tid>>1, comp = tid&1)
    float c_st = 0.f;
    if (tid < 128 && half == 0) h_s[g] = 0ull;   // g = tid>>1 < 64
    __syncthreads();

    const ull* xp_ptr = (const ull*)g_xproj;
    const size_t idx0 = (size_t)bp * GSZ + g;
    ull xp_cur = 0ull;
    if (!half) xp_cur = xp_ptr[idx0];            // t = 0, even lane only

    for (int t = 0; t < T_SEQ; ++t) {
        // prefetch next step's x_proj (even lane only)
        ull xp_next = 0ull;
        if (!half && (t + 1 < T_SEQ))
            xp_next = xp_ptr[idx0 + (size_t)(t + 1) * (NBP * GSZ)];

        // partial gate sum over this thread's 32 k-values (packed batch pair)
        ull acc0 = 0ull, acc1 = 0ull, acc2 = 0ull, acc3 = 0ull;
        const ulonglong2* h2 = (const ulonglong2*)h_s + half * 16;
        #pragma unroll
        for (int kk = 0; kk < 16; kk += 2) {
            ulonglong2 ha = h2[kk];
            ulonglong2 hb = h2[kk + 1];
            acc0 = ffma2(w2[2 * kk + 0], ha.x, acc0);
            acc1 = ffma2(w2[2 * kk + 1], ha.y, acc1);
            acc2 = ffma2(w2[2 * kk + 2], hb.x, acc2);
            acc3 = ffma2(w2[2 * kk + 3], hb.y, acc3);
        }
        ull part = fadd2(fadd2(acc0, acc1), fadd2(acc2, acc3));
        if (!half) part = fadd2(part, xp_cur);
        xp_cur = xp_next;

        // combine k-halves (partner lane = lane^1, same g)
        ull other = __shfl_xor_sync(0xffffffffu, part, 1);
        float2 gv = unpack2(fadd2(part, other));

        // split activation: even lane does comp x, odd does comp y
        float v = half ? gv.y : gv.x;
        float r = (sec == 2) ? tanh_f(v) : sigm_f(v);
        float rp = __shfl_xor_sync(0xffffffffu, r, 1);
        if (!half) gate_s[g] = pack2(r, rp);
        __syncthreads();

        // h-update: 128 threads, one (j, component) each
        if (tid < 128) {
            const int j  = tid >> 1;
            const int cm = tid & 1;
            const float* gsf = (const float*)gate_s;
            float iv = gsf[(      j) * 2 + cm];
            float fv = gsf[( 64 + j) * 2 + cm];
            float gg = gsf[(128 + j) * 2 + cm];
            float ov = gsf[(192 + j) * 2 + cm];
            c_st = fmaf(fv, c_st, iv * gg);
            float h = ov * tanh_f(c_st);
            ((float*)h_s)[j * 2 + cm] = h;
            if (t == T_SEQ - 1)
                ((float*)g_hT)[((bp << 6) + j) * 2 + cm] = h;
        }
        __syncthreads();
    }
}

// =====================================================================
// Kernel C: logits = h_T @ W_cls^T + b_cls   (256 x 10)
// =====================================================================
__global__ void cls_kernel(const float* __restrict__ W_cls,
                           const float* __restrict__ b_cls,
                           float* __restrict__ out)
{
    const int b = blockIdx.x, lane = threadIdx.x;
    const int bp = b >> 1, par = b & 1;
    float2 p0 = unpack2(g_hT[bp * HSZ + lane]);
    float2 p1 = unpack2(g_hT[bp * HSZ + lane + 32]);
    float h0 = par ? p0.y : p0.x;
    float h1 = par ? p1.y : p1.x;
    #pragma unroll
    for (int c = 0; c < NCLS; ++c) {
        float p = h0 * W_cls[c * HSZ + lane] + h1 * W_cls[c * HSZ + lane + 32];
        #pragma unroll
        for (int off = 16; off; off >>= 1)
            p += __shfl_xor_sync(0xffffffffu, p, off);
        if (lane == 0) out[b * NCLS + c] = p + b_cls[c];
    }
}

// =====================================================================
extern "C" void kernel_launch(void* const* d_in, const int* in_sizes, int n_in,
                              void* d_out, int out_size) {
    const float* x     = (const float*)d_in[0];
    const float* W_ih  = (const float*)d_in[1];
    const float* W_hh  = (const float*)d_in[2];
    const float* b_ih  = (const float*)d_in[3];
    const float* b_hh  = (const float*)d_in[4];
    const float* W_cls = (const float*)d_in[5];
    const float* b_cls = (const float*)d_in[6];
    float* out = (float*)d_out;

    dim3 gA(2, 64, 128);               // g-tiles x t-tiles x batch-pairs
    xproj_kernel<<<gA, 128>>>(x, W_ih, b_ih, b_hh);
    lstm_kernel<<<NBP, 512>>>(W_hh);
    cls_kernel<<<BATCH, 32>>>(W_cls, b_cls, out);
}

// round 10
// speedup vs baseline: 1.5182x; 1.5182x over previous
#include <cuda_runtime.h>
#include <cstdint>

#define T_SEQ 1024
#define BATCH 256
#define ISZ   128
#define HSZ   64
#define GSZ   256   // 4*H
#define NBP   128   // BATCH/2 (batch pairs)
#define NCLS  10

typedef unsigned long long ull;

// Scratch (device globals — allocation-free per harness rules)
// Layout: [t][bp][g] of float2{batch 2bp, batch 2bp+1}
__device__ float2 g_xproj[(size_t)T_SEQ * NBP * GSZ];   // 268 MB
__device__ ull    g_hT[NBP * HSZ];                      // final hidden, packed pairs

// ---------- helpers ----------
union F2U { float2 f2; ull u; };

__device__ __forceinline__ ull pack2(float lo, float hi) {
    F2U t; t.f2 = make_float2(lo, hi); return t.u;
}
__device__ __forceinline__ float2 unpack2(ull v) {
    F2U t; t.u = v; return t.f2;
}
__device__ __forceinline__ ull ffma2(ull a, ull b, ull c) {
    ull d;
    asm("fma.rn.f32x2 %0, %1, %2, %3;" : "=l"(d) : "l"(a), "l"(b), "l"(c));
    return d;
}
__device__ __forceinline__ ull fadd2(ull a, ull b) {
    ull d;
    asm("add.rn.f32x2 %0, %1, %2;" : "=l"(d) : "l"(a), "l"(b));
    return d;
}
__device__ __forceinline__ unsigned f2tf32(float f) {
    unsigned r;
    asm("cvt.rna.tf32.f32 %0, %1;" : "=r"(r) : "f"(f));
    return r;
}
__device__ __forceinline__ float ex2_ap(float x) {
    float y; asm("ex2.approx.f32 %0, %1;" : "=f"(y) : "f"(x)); return y;
}
__device__ __forceinline__ float rcp_ap(float x) {
    float y; asm("rcp.approx.f32 %0, %1;" : "=f"(y) : "f"(x)); return y;
}
// tanh for the h-update (leader-only): tanh(x) = 1 - 2/(1+2^(x*2*log2e))
__device__ __forceinline__ float tanh_f(float x) {
    return fmaf(-2.0f, rcp_ap(1.0f + ex2_ap(2.8853900817779268f * x)), 1.0f);
}

// =====================================================================
// Kernel A: x_proj — EXACT round-1 version (measured 207us, 96 regs).
// tf32 mma.sync, CTA tile: 16 t-rows x 128 g-cols x 2 batches, K chunked 64.
// =====================================================================
__global__ __launch_bounds__(128) void xproj_kernel(
    const float* __restrict__ x, const float* __restrict__ W_ih,
    const float* __restrict__ b_ih, const float* __restrict__ b_hh)
{
    __shared__ float As[2][16][68];     // [batch][t][k] pad->68
    __shared__ float Ws[128][68];       // [g][k]
    __shared__ float bias_s[128];

    const int tid  = threadIdx.x;
    const int warp = tid >> 5, lane = tid & 31;
    const int gid  = lane >> 2, tig = lane & 3;
    const int gbase = blockIdx.x * 128;
    const int t0    = blockIdx.y * 16;
    const int bp    = blockIdx.z;
    const int b0g   = bp * 2;

    bias_s[tid] = b_ih[gbase + tid] + b_hh[gbase + tid];

    float acc[2][4][4];
    #pragma unroll
    for (int b = 0; b < 2; b++)
        #pragma unroll
        for (int n = 0; n < 4; n++)
            #pragma unroll
            for (int i = 0; i < 4; i++) acc[b][n][i] = 0.f;

    for (int kc = 0; kc < 128; kc += 64) {
        #pragma unroll
        for (int r = 0; r < 4; ++r) {
            int idx = tid + r * 128;
            int b   = idx >> 8;
            int rem = idx & 255;
            int tt  = rem >> 4;
            int v   = rem & 15;
            float4 src = *(const float4*)&x[(((size_t)(b0g + b)) * T_SEQ + (t0 + tt)) * ISZ + kc + v * 4];
            *(float4*)&As[b][tt][v * 4] = src;
        }
        #pragma unroll
        for (int r = 0; r < 16; ++r) {
            int idx = tid + r * 128;
            int gg  = idx >> 4;
            int v   = idx & 15;
            float4 src = *(const float4*)&W_ih[((size_t)(gbase + gg)) * ISZ + kc + v * 4];
            *(float4*)&Ws[gg][v * 4] = src;
        }
        __syncthreads();

        #pragma unroll
        for (int ks = 0; ks < 8; ++ks) {
            const int k0 = ks * 8;
            unsigned a[2][4];
            #pragma unroll
            for (int b = 0; b < 2; b++) {
                a[b][0] = f2tf32(As[b][gid    ][k0 + tig]);
                a[b][1] = f2tf32(As[b][gid + 8][k0 + tig]);
                a[b][2] = f2tf32(As[b][gid    ][k0 + tig + 4]);
                a[b][3] = f2tf32(As[b][gid + 8][k0 + tig + 4]);
            }
            #pragma unroll
            for (int nt = 0; nt < 4; nt++) {
                const int nl = warp * 32 + nt * 8 + gid;
                unsigned bb0 = f2tf32(Ws[nl][k0 + tig]);
                unsigned bb1 = f2tf32(Ws[nl][k0 + tig + 4]);
                #pragma unroll
                for (int b = 0; b < 2; b++) {
                    asm volatile(
                        "mma.sync.aligned.m16n8k8.row.col.f32.tf32.tf32.f32 "
                        "{%0,%1,%2,%3}, {%4,%5,%6,%7}, {%8,%9}, {%0,%1,%2,%3};"
                        : "+f"(acc[b][nt][0]), "+f"(acc[b][nt][1]),
                          "+f"(acc[b][nt][2]), "+f"(acc[b][nt][3])
                        : "r"(a[b][0]), "r"(a[b][1]), "r"(a[b][2]), "r"(a[b][3]),
                          "r"(bb0), "r"(bb1));
                }
            }
        }
        __syncthreads();
    }

    #pragma unroll
    for (int nt = 0; nt < 4; nt++) {
        const int nl  = warp * 32 + nt * 8 + 2 * tig;
        const float bs0 = bias_s[nl], bs1 = bias_s[nl + 1];
        const int ggl = gbase + nl;
        const int tr0 = t0 + gid, tr1 = t0 + gid + 8;
        float4 v0 = make_float4(acc[0][nt][0] + bs0, acc[1][nt][0] + bs0,
                                acc[0][nt][1] + bs1, acc[1][nt][1] + bs1);
        float4 v1 = make_float4(acc[0][nt][2] + bs0, acc[1][nt][2] + bs0,
                                acc[0][nt][3] + bs1, acc[1][nt][3] + bs1);
        *(float4*)&g_xproj[((size_t)tr0 * NBP + bp) * GSZ + ggl] = v0;
        *(float4*)&g_xproj[((size_t)tr1 * NBP + bp) * GSZ + ggl] = v1;
    }
}

// =====================================================================
// Kernel B: recurrence. 128 CTAs (one batch pair), 256 threads.
// tid = 4*j + gate: the 4 gates of hidden unit j are adjacent lanes.
// Gates gather to quad leader via 3 overlapped butterfly shuffles
// (no gate SMEM round-trip). h double-buffered => ONE barrier per step.
// Branch-free fast activations: sigmoid via ex2+rcp; tanh = 2*sigm(2x)-1.
// =====================================================================
__global__ __launch_bounds__(256, 1) void lstm_kernel(const float* __restrict__ W_hh)
{
    __shared__ __align__(16) ull h_s[2][HSZ];   // double-buffered hidden state

    const int tid  = threadIdx.x;
    const int j    = tid >> 2;        // hidden unit 0..63
    const int gate = tid & 3;         // 0:i 1:f 2:g 3:o
    const int bp   = blockIdx.x;
    const int grow = (gate << 6) | j; // row in [4H] gate-major order

    // branch-free activation constants: r = aco * sigm(kmul*x) + bco
    const float kmul = (gate == 2) ? 2.8853900817779268f : 1.4426950408889634f;
    const float aco  = (gate == 2) ?  2.0f : 1.0f;
    const float bco  = (gate == 2) ? -1.0f : 0.0f;

    // W_hh row for this gate-row, duplicated into f32x2 pairs (128 regs)
    ull w2[HSZ];
    {
        const float4* wrow = (const float4*)&W_hh[grow * HSZ];
        #pragma unroll
        for (int q = 0; q < 16; ++q) {
            float4 w = wrow[q];
            w2[q * 4 + 0] = pack2(w.x, w.x);
            w2[q * 4 + 1] = pack2(w.y, w.y);
            w2[q * 4 + 2] = pack2(w.z, w.z);
            w2[q * 4 + 3] = pack2(w.w, w.w);
        }
    }

    float c0 = 0.f, c1 = 0.f;         // cell state (quad leaders only)
    if (tid < HSZ) h_s[0][tid] = 0ull;
    __syncthreads();

    const ull* xp_ptr = (const ull*)g_xproj;
    const size_t idx0 = (size_t)bp * GSZ + grow;
    const size_t tstp = (size_t)NBP * GSZ;
    ull xp_cur = xp_ptr[idx0];              // t = 0
    ull xp_n1  = xp_ptr[idx0 + tstp];       // t = 1 (depth-2 prefetch)

    for (int t = 0; t < T_SEQ; ++t) {
        // prefetch t+2 (step time < DRAM latency, so depth-2)
        ull xp_n2 = 0ull;
        if (t + 2 < T_SEQ) xp_n2 = xp_ptr[idx0 + (size_t)(t + 2) * tstp];

        // gate dot product over h (packed batch pair), 4-acc ILP
        const ulonglong2* h2 = (const ulonglong2*)h_s[t & 1];
        ull acc0 = 0ull, acc1 = 0ull, acc2 = 0ull, acc3 = 0ull;
        #pragma unroll
        for (int kk = 0; kk < 16; ++kk) {
            ulonglong2 ha = h2[2 * kk];
            ulonglong2 hb = h2[2 * kk + 1];
            acc0 = ffma2(w2[4 * kk + 0], ha.x, acc0);
            acc1 = ffma2(w2[4 * kk + 1], ha.y, acc1);
            acc2 = ffma2(w2[4 * kk + 2], hb.x, acc2);
            acc3 = ffma2(w2[4 * kk + 3], hb.y, acc3);
        }
        ull gsum = fadd2(fadd2(acc0, acc1), fadd2(acc2, acc3));
        gsum = fadd2(gsum, xp_cur);
        xp_cur = xp_n1; xp_n1 = xp_n2;

        // branch-free activation for both batch components
        float2 gv = unpack2(gsum);
        float r0 = fmaf(aco, rcp_ap(1.0f + ex2_ap(-kmul * gv.x)), bco);
        float r1 = fmaf(aco, rcp_ap(1.0f + ex2_ap(-kmul * gv.y)), bco);
        ull rp = pack2(r0, r1);

        // butterfly gather: every lane ends with gate^1, gate^2, gate^3 values
        ull v1 = __shfl_xor_sync(0xffffffffu, rp, 1);   // gate^1
        ull v2 = __shfl_xor_sync(0xffffffffu, rp, 2);   // gate^2
        ull v3 = __shfl_xor_sync(0xffffffffu, v1, 2);   // gate^3

        if (gate == 0) {                 // leader: rp=i, v1=f, v2=g, v3=o
            float2 iv = unpack2(rp);
            float2 fv = unpack2(v1);
            float2 gg = unpack2(v2);
            float2 ov = unpack2(v3);
            c0 = fmaf(fv.x, c0, iv.x * gg.x);
            c1 = fmaf(fv.y, c1, iv.y * gg.y);
            float h0 = ov.x * tanh_f(c0);
            float h1 = ov.y * tanh_f(c1);
            ull hp = pack2(h0, h1);
            h_s[(t & 1) ^ 1][j] = hp;    // write NEXT buffer
            if (t == T_SEQ - 1) g_hT[bp * HSZ + j] = hp;
        }
        __syncthreads();                 // single barrier per step
    }
}

// =====================================================================
// Kernel C: logits = h_T @ W_cls^T + b_cls   (256 x 10)
// =====================================================================
__global__ void cls_kernel(const float* __restrict__ W_cls,
                           const float* __restrict__ b_cls,
                           float* __restrict__ out)
{
    const int b = blockIdx.x, lane = threadIdx.x;
    const int bp = b >> 1, par = b & 1;
    float2 p0 = unpack2(g_hT[bp * HSZ + lane]);
    float2 p1 = unpack2(g_hT[bp * HSZ + lane + 32]);
    float h0 = par ? p0.y : p0.x;
    float h1 = par ? p1.y : p1.x;
    #pragma unroll
    for (int c = 0; c < NCLS; ++c) {
        float p = h0 * W_cls[c * HSZ + lane] + h1 * W_cls[c * HSZ + lane + 32];
        #pragma unroll
        for (int off = 16; off; off >>= 1)
            p += __shfl_xor_sync(0xffffffffu, p, off);
        if (lane == 0) out[b * NCLS + c] = p + b_cls[c];
    }
}

// =====================================================================
extern "C" void kernel_launch(void* const* d_in, const int* in_sizes, int n_in,
                              void* d_out, int out_size) {
    const float* x     = (const float*)d_in[0];
    const float* W_ih  = (const float*)d_in[1];
    const float* W_hh  = (const float*)d_in[2];
    const float* b_ih  = (const float*)d_in[3];
    const float* b_hh  = (const float*)d_in[4];
    const float* W_cls = (const float*)d_in[5];
    const float* b_cls = (const float*)d_in[6];
    float* out = (float*)d_out;

    dim3 gA(2, 64, 128);               // g-tiles x t-tiles x batch-pairs
    xproj_kernel<<<gA, 128>>>(x, W_ih, b_ih, b_hh);
    lstm_kernel<<<NBP, 256>>>(W_hh);
    cls_kernel<<<BATCH, 32>>>(W_cls, b_cls, out);
}

// round 11
// speedup vs baseline: 1.6915x; 1.1142x over previous
#include <cuda_runtime.h>
#include <cstdint>

#define T_SEQ 1024
#define BATCH 256
#define ISZ   128
#define HSZ   64
#define GSZ   256   // 4*H
#define NBP   128   // BATCH/2 (batch pairs)
#define NCLS  10

typedef unsigned long long ull;

// Scratch (device globals — allocation-free per harness rules)
// Layout: [t][bp][g] of float2{batch 2bp, batch 2bp+1}
__device__ float2 g_xproj[(size_t)T_SEQ * NBP * GSZ];   // 268 MB
__device__ ull    g_hT[NBP * HSZ];                      // final hidden, packed pairs

// ---------- helpers ----------
union F2U { float2 f2; ull u; };

__device__ __forceinline__ ull pack2(float lo, float hi) {
    F2U t; t.f2 = make_float2(lo, hi); return t.u;
}
__device__ __forceinline__ float2 unpack2(ull v) {
    F2U t; t.u = v; return t.f2;
}
__device__ __forceinline__ ull ffma2(ull a, ull b, ull c) {
    ull d;
    asm("fma.rn.f32x2 %0, %1, %2, %3;" : "=l"(d) : "l"(a), "l"(b), "l"(c));
    return d;
}
__device__ __forceinline__ ull fadd2(ull a, ull b) {
    ull d;
    asm("add.rn.f32x2 %0, %1, %2;" : "=l"(d) : "l"(a), "l"(b));
    return d;
}
__device__ __forceinline__ unsigned f2tf32(float f) {
    unsigned r;
    asm("cvt.rna.tf32.f32 %0, %1;" : "=r"(r) : "f"(f));
    return r;
}
__device__ __forceinline__ float ex2_ap(float x) {
    float y; asm("ex2.approx.f32 %0, %1;" : "=f"(y) : "f"(x)); return y;
}
__device__ __forceinline__ float rcp_ap(float x) {
    float y; asm("rcp.approx.f32 %0, %1;" : "=f"(y) : "f"(x)); return y;
}
// sigmoid(x) = 1/(1+2^(-x*log2e)) : FMUL + MUFU + FADD + MUFU, branch-free
__device__ __forceinline__ float sigm_f(float x) {
    return rcp_ap(1.0f + ex2_ap(-1.4426950408889634f * x));
}
// tanh(x) = 1 - 2/(1+2^(2x*log2e)) : branch-free, ~44 cyc vs libm ~150+
__device__ __forceinline__ float tanh_f(float x) {
    return fmaf(-2.0f, rcp_ap(1.0f + ex2_ap(2.8853900817779268f * x)), 1.0f);
}

// =====================================================================
// Kernel A: x_proj — EXACT round-1 version (measured 207-208us, 96 regs).
// =====================================================================
__global__ __launch_bounds__(128) void xproj_kernel(
    const float* __restrict__ x, const float* __restrict__ W_ih,
    const float* __restrict__ b_ih, const float* __restrict__ b_hh)
{
    __shared__ float As[2][16][68];
    __shared__ float Ws[128][68];
    __shared__ float bias_s[128];

    const int tid  = threadIdx.x;
    const int warp = tid >> 5, lane = tid & 31;
    const int gid  = lane >> 2, tig = lane & 3;
    const int gbase = blockIdx.x * 128;
    const int t0    = blockIdx.y * 16;
    const int bp    = blockIdx.z;
    const int b0g   = bp * 2;

    bias_s[tid] = b_ih[gbase + tid] + b_hh[gbase + tid];

    float acc[2][4][4];
    #pragma unroll
    for (int b = 0; b < 2; b++)
        #pragma unroll
        for (int n = 0; n < 4; n++)
            #pragma unroll
            for (int i = 0; i < 4; i++) acc[b][n][i] = 0.f;

    for (int kc = 0; kc < 128; kc += 64) {
        #pragma unroll
        for (int r = 0; r < 4; ++r) {
            int idx = tid + r * 128;
            int b   = idx >> 8;
            int rem = idx & 255;
            int tt  = rem >> 4;
            int v   = rem & 15;
            float4 src = *(const float4*)&x[(((size_t)(b0g + b)) * T_SEQ + (t0 + tt)) * ISZ + kc + v * 4];
            *(float4*)&As[b][tt][v * 4] = src;
        }
        #pragma unroll
        for (int r = 0; r < 16; ++r) {
            int idx = tid + r * 128;
            int gg  = idx >> 4;
            int v   = idx & 15;
            float4 src = *(const float4*)&W_ih[((size_t)(gbase + gg)) * ISZ + kc + v * 4];
            *(float4*)&Ws[gg][v * 4] = src;
        }
        __syncthreads();

        #pragma unroll
        for (int ks = 0; ks < 8; ++ks) {
            const int k0 = ks * 8;
            unsigned a[2][4];
            #pragma unroll
            for (int b = 0; b < 2; b++) {
                a[b][0] = f2tf32(As[b][gid    ][k0 + tig]);
                a[b][1] = f2tf32(As[b][gid + 8][k0 + tig]);
                a[b][2] = f2tf32(As[b][gid    ][k0 + tig + 4]);
                a[b][3] = f2tf32(As[b][gid + 8][k0 + tig + 4]);
            }
            #pragma unroll
            for (int nt = 0; nt < 4; nt++) {
                const int nl = warp * 32 + nt * 8 + gid;
                unsigned bb0 = f2tf32(Ws[nl][k0 + tig]);
                unsigned bb1 = f2tf32(Ws[nl][k0 + tig + 4]);
                #pragma unroll
                for (int b = 0; b < 2; b++) {
                    asm volatile(
                        "mma.sync.aligned.m16n8k8.row.col.f32.tf32.tf32.f32 "
                        "{%0,%1,%2,%3}, {%4,%5,%6,%7}, {%8,%9}, {%0,%1,%2,%3};"
                        : "+f"(acc[b][nt][0]), "+f"(acc[b][nt][1]),
                          "+f"(acc[b][nt][2]), "+f"(acc[b][nt][3])
                        : "r"(a[b][0]), "r"(a[b][1]), "r"(a[b][2]), "r"(a[b][3]),
                          "r"(bb0), "r"(bb1));
                }
            }
        }
        __syncthreads();
    }

    #pragma unroll
    for (int nt = 0; nt < 4; nt++) {
        const int nl  = warp * 32 + nt * 8 + 2 * tig;
        const float bs0 = bias_s[nl], bs1 = bias_s[nl + 1];
        const int ggl = gbase + nl;
        const int tr0 = t0 + gid, tr1 = t0 + gid + 8;
        float4 v0 = make_float4(acc[0][nt][0] + bs0, acc[1][nt][0] + bs0,
                                acc[0][nt][1] + bs1, acc[1][nt][1] + bs1);
        float4 v1 = make_float4(acc[0][nt][2] + bs0, acc[1][nt][2] + bs0,
                                acc[0][nt][3] + bs1, acc[1][nt][3] + bs1);
        *(float4*)&g_xproj[((size_t)tr0 * NBP + bp) * GSZ + ggl] = v0;
        *(float4*)&g_xproj[((size_t)tr1 * NBP + bp) * GSZ + ggl] = v1;
    }
}

// =====================================================================
// Kernel B: recurrence — ROUND-1 structure (measured 555us) with ONLY
// the activations swapped to branch-free MUFU forms + depth-2 prefetch.
// 128 CTAs (one batch pair), 256 threads, thread g = gate-row g.
// =====================================================================
__global__ __launch_bounds__(256, 1) void lstm_kernel(const float* __restrict__ W_hh)
{
    __shared__ __align__(16) ull h_s[HSZ];
    __shared__ ull gate_s[GSZ];

    const int g   = threadIdx.x;
    const int bp  = blockIdx.x;
    const int j   = g & 63;
    const int sec = g >> 6;          // 0:i 1:f 2:g 3:o (warp-uniform)

    // branch-free activation constants: r = aco * sigm(kmul*x) + bco
    const float kmul = (sec == 2) ? 2.8853900817779268f : 1.4426950408889634f;
    const float aco  = (sec == 2) ?  2.0f : 1.0f;
    const float bco  = (sec == 2) ? -1.0f : 0.0f;

    // Load W_hh row g, duplicated into f32x2 pairs (128 registers)
    ull w2[HSZ];
    {
        const float4* wrow = (const float4*)&W_hh[g * HSZ];
        #pragma unroll
        for (int q = 0; q < 16; ++q) {
            float4 w = wrow[q];
            w2[q * 4 + 0] = pack2(w.x, w.x);
            w2[q * 4 + 1] = pack2(w.y, w.y);
            w2[q * 4 + 2] = pack2(w.z, w.z);
            w2[q * 4 + 3] = pack2(w.w, w.w);
        }
    }

    float c0 = 0.f, c1 = 0.f;
    if (g < HSZ) h_s[g] = 0ull;
    __syncthreads();

    const ull* xp_ptr = (const ull*)g_xproj;
    const size_t idx0 = (size_t)bp * GSZ + g;
    const size_t tstp = (size_t)NBP * GSZ;
    ull xp_cur = xp_ptr[idx0];              // t = 0
    ull xp_n1  = xp_ptr[idx0 + tstp];       // t = 1 (depth-2 prefetch)

    for (int t = 0; t < T_SEQ; ++t) {
        ull xp_n2 = 0ull;
        if (t + 2 < T_SEQ) xp_n2 = xp_ptr[idx0 + (size_t)(t + 2) * tstp];

        // gates[g] = xp + sum_k W_hh[g][k] * h[k]   (packed over the batch pair)
        ull acc0 = 0ull, acc1 = 0ull, acc2 = 0ull, acc3 = 0ull;
        const ulonglong2* h2 = (const ulonglong2*)h_s;
        #pragma unroll
        for (int kk = 0; kk < 16; ++kk) {
            ulonglong2 ha = h2[2 * kk];
            ulonglong2 hb = h2[2 * kk + 1];
            acc0 = ffma2(w2[4 * kk + 0], ha.x, acc0);
            acc1 = ffma2(w2[4 * kk + 1], ha.y, acc1);
            acc2 = ffma2(w2[4 * kk + 2], hb.x, acc2);
            acc3 = ffma2(w2[4 * kk + 3], hb.y, acc3);
        }
        ull gsum = fadd2(fadd2(acc0, acc1), fadd2(acc2, acc3));
        gsum = fadd2(gsum, xp_cur);
        xp_cur = xp_n1; xp_n1 = xp_n2;

        // branch-free activation (was: divergent tanhf / __expf+div)
        float2 gv = unpack2(gsum);
        float r0 = fmaf(aco, rcp_ap(1.0f + ex2_ap(-kmul * gv.x)), bco);
        float r1 = fmaf(aco, rcp_ap(1.0f + ex2_ap(-kmul * gv.y)), bco);
        gate_s[g] = pack2(r0, r1);
        __syncthreads();

        if (g < HSZ) {
            float2 iv = unpack2(gate_s[j]);
            float2 fv = unpack2(gate_s[64 + j]);
            float2 gg = unpack2(gate_s[128 + j]);
            float2 ov = unpack2(gate_s[192 + j]);
            c0 = fmaf(fv.x, c0, iv.x * gg.x);
            c1 = fmaf(fv.y, c1, iv.y * gg.y);
            float h0 = ov.x * tanh_f(c0);      // was libm tanhf
            float h1 = ov.y * tanh_f(c1);
            ull hp = pack2(h0, h1);
            h_s[j] = hp;
            if (t == T_SEQ - 1) g_hT[bp * HSZ + j] = hp;
        }
        __syncthreads();
    }
}

// =====================================================================
// Kernel C: logits = h_T @ W_cls^T + b_cls   (256 x 10)
// =====================================================================
__global__ void cls_kernel(const float* __restrict__ W_cls,
                           const float* __restrict__ b_cls,
                           float* __restrict__ out)
{
    const int b = blockIdx.x, lane = threadIdx.x;
    const int bp = b >> 1, par = b & 1;
    float2 p0 = unpack2(g_hT[bp * HSZ + lane]);
    float2 p1 = unpack2(g_hT[bp * HSZ + lane + 32]);
    float h0 = par ? p0.y : p0.x;
    float h1 = par ? p1.y : p1.x;
    #pragma unroll
    for (int c = 0; c < NCLS; ++c) {
        float p = h0 * W_cls[c * HSZ + lane] + h1 * W_cls[c * HSZ + lane + 32];
        #pragma unroll
        for (int off = 16; off; off >>= 1)
            p += __shfl_xor_sync(0xffffffffu, p, off);
        if (lane == 0) out[b * NCLS + c] = p + b_cls[c];
    }
}

// =====================================================================
extern "C" void kernel_launch(void* const* d_in, const int* in_sizes, int n_in,
                              void* d_out, int out_size) {
    const float* x     = (const float*)d_in[0];
    const float* W_ih  = (const float*)d_in[1];
    const float* W_hh  = (const float*)d_in[2];
    const float* b_ih  = (const float*)d_in[3];
    const float* b_hh  = (const float*)d_in[4];
    const float* W_cls = (const float*)d_in[5];
    const float* b_cls = (const float*)d_in[6];
    float* out = (float*)d_out;

    dim3 gA(2, 64, 128);               // g-tiles x t-tiles x batch-pairs
    xproj_kernel<<<gA, 128>>>(x, W_ih, b_ih, b_hh);
    lstm_kernel<<<NBP, 256>>>(W_hh);
    cls_kernel<<<BATCH, 32>>>(W_cls, b_cls, out);
}